// round 15
// baseline (speedup 1.0000x reference)
#include <cuda_runtime.h>
#include <cuda_fp16.h>
#include <math.h>

#define CCH  32
#define HF   256
#define WF   256
#define MAXW 128
#define MBOX 1024
#define IMG_WORDS (32u * 65536u)           // elements per image (C*H*W)
#define NB_PREP 4
#define NB_RANK 128

// 67 MB transposed feature map scratch: layout (N, H, W, C), C contiguous, fp16.
// Fits in L2 (126 MB) -> sampler gathers are L2 hits; output writes stream.
__device__ __half g_fmt[16u * IMG_WORDS];

__device__ float g_p1x[MBOX], g_p1y[MBOX];
__device__ float g_axx[MBOX], g_axy[MBOX];
__device__ float g_ayx[MBOX], g_ayy[MBOX];
__device__ int   g_width[MBOX];
__device__ int   g_order[MBOX];
__device__ int4  g_bbox[MBOX];     // xmin, xmax, ymin, ymax (feature px, +margin)
__device__ int   g_map[MBOX];      // mapping (or -1 past M)
__device__ int   g_prep_done;      // release flag (reset by sampler each run)

// ---------------------------------------------------------------------------
// Kernel 1: fused prep + rank + transpose.
//   bids [0,4):    prep — width (bit-identical math), geometry, bbox, map;
//                  releases g_prep_done.  Dispatched first, never waits.
//   bids [4,132):  stable descending-width rank (waits for prep, ~1us).
//   bids [132,..): transpose w/ bbox tile-skip (waits for prep, ~1us).
// ---------------------------------------------------------------------------
__global__ __launch_bounds__(256) void fused_prep_transpose_rank_kernel(
    const float* __restrict__ fm, const float* __restrict__ boxes,
    const int* __restrict__ mapping, float* __restrict__ out_tail,
    int M, int write_tail)
{
    const int bid  = blockIdx.x;
    const int tid  = threadIdx.x;
    const int lane = tid & 31;
    const int wrp  = tid >> 5;

    if (bid < NB_PREP) {
        // ---------------- prep part ----------------
        const int i = bid * 256 + tid;
        if (i < M) {
            const float* b = boxes + i * 8;
            float p1x = b[0]*0.25f, p1y = b[1]*0.25f;
            float p2x = b[2]*0.25f, p2y = b[3]*0.25f;
            float p4x = b[6]*0.25f, p4y = b[7]*0.25f;
            float dx2 = __fadd_rn(p2x,-p1x), dy2 = __fadd_rn(p2y,-p1y);
            float dx4 = __fadd_rn(p4x,-p1x), dy4 = __fadd_rn(p4y,-p1y);
            float bw = __fsqrt_rn(__fadd_rn(__fmul_rn(dx2,dx2), __fmul_rn(dy2,dy2)));
            float bh = __fsqrt_rn(__fadd_rn(__fmul_rn(dx4,dx4), __fmul_rn(dy4,dy4)));
            float bmaj = bw, bmin = bh;
            if (bw <= bh) { bmaj = bh; bmin = bw; }
            float ratio = __fdiv_rn(__fmul_rn(8.0f, bmaj), fmaxf(bmin, 1e-6f));
            int w = (int)fminf(fmaxf(ceilf(ratio), 1.0f), 128.0f);

            float wf = (float)w;
            g_width[i] = w;
            g_p1x[i] = p1x; g_p1y[i] = p1y;
            g_axx[i] = __fdiv_rn(dx2, wf);
            g_axy[i] = __fdiv_rn(dy2, wf);
            g_ayx[i] = dx4 * 0.125f;
            g_ayy[i] = dy4 * 0.125f;

            float p3x = p2x + p4x - p1x, p3y = p2y + p4y - p1y;
            float xmn = fminf(fminf(p1x, p2x), fminf(p4x, p3x));
            float xmx = fmaxf(fmaxf(p1x, p2x), fmaxf(p4x, p3x));
            float ymn = fminf(fminf(p1y, p2y), fminf(p4y, p3y));
            float ymx = fmaxf(fmaxf(p1y, p2y), fmaxf(p4y, p3y));
            g_bbox[i] = make_int4((int)floorf(xmn) - 2, (int)ceilf(xmx) + 2,
                                  (int)floorf(ymn) - 2, (int)ceilf(ymx) + 2);
            g_map[i] = mapping[i];
        } else {
            g_map[i]  = -1;
            g_bbox[i] = make_int4(1 << 30, -(1 << 30), 1 << 30, -(1 << 30));
        }
        __syncthreads();
        if (tid == 0) { __threadfence(); atomicAdd(&g_prep_done, 1); }
        return;
    }

    // acquire: wait for prep (bids 0-3, dispatched first; ~1us)
    if (tid == 0) {
        volatile int* pd = &g_prep_done;
        while (*pd < NB_PREP) __nanosleep(64);
    }
    __syncthreads();
    __threadfence();

    if (bid < NB_PREP + NB_RANK) {
        // ---------------- rank part ----------------
        __shared__ int sw[MBOX];
        for (int i = tid; i < MBOX; i += 256)
            sw[i] = (i < M) ? g_width[i] : -1;
        __syncthreads();
        const int i = (bid - NB_PREP) * 8 + wrp;
        if (i < M) {
            const int w = sw[i];
            int rank = 0;
            #pragma unroll 4
            for (int t = 0; t < MBOX / 32; t++) {
                int j = t * 32 + lane;
                int wj = sw[j];
                rank += (wj > w) | ((wj == w) & (j < i));
            }
            #pragma unroll
            for (int o = 16; o; o >>= 1)
                rank += __shfl_xor_sync(0xffffffffu, rank, o);
            if (lane == 0) {
                g_order[rank] = i;
                if (write_tail) {
                    out_tail[rank]     = (float)w;
                    out_tail[M + rank] = (float)i;
                }
            }
        }
        return;
    }

    // ---------------- transpose part ----------------
    const int px0 = (bid - NB_PREP - NB_RANK) << 6;   // 64 px per block
    const int n   = px0 >> 16;
    const int pxi = px0 & 65535;
    const int row = pxi >> 8;
    const int xq0 = pxi & 255;                // 0,64,128,192

    // skip test: does any box of image n touch this row-quarter?
    int pred = 0;
    #pragma unroll
    for (int t = 0; t < 4; t++) {
        const int bix = tid + (t << 8);
        const int4 bb = g_bbox[bix];
        const int  mp = g_map[bix];
        pred |= (mp == n) & (row >= bb.z) & (row <= bb.w)
                          & (xq0 <= bb.y) & (xq0 + 63 >= bb.x);
    }
    if (!__syncthreads_or(pred)) return;

    __shared__ float tile[32][65];
    const size_t ibase = (size_t)n * IMG_WORDS;

    // read: coalesced along W (read-once, evict-first)
    #pragma unroll
    for (int t = 0; t < 4; t++) {
        const int cc = wrp + t * 8;
        const float* src = fm + ibase + ((size_t)cc << 16) + pxi;
        tile[cc][lane]      = __ldcs(src + lane);
        tile[cc][lane + 32] = __ldcs(src + lane + 32);
    }
    __syncthreads();

    // write: coalesced along C, __half2 per lane (default policy: keep in L2)
    const int c0 = (lane & 15) << 1;
    const int pp = lane >> 4;
    __half* const dstb = g_fmt + ibase + ((size_t)pxi << 5) + c0;
    #pragma unroll
    for (int t = 0; t < 4; t++) {
        const int p0 = ((wrp + t * 8) << 1) + pp;     // 0..63
        __half2 v = __floats2half2_rn(tile[c0][p0], tile[c0 + 1][p0]);
        *(__half2*)(dstb + ((size_t)p0 << 5)) = v;
    }
}

// ---------------------------------------------------------------------------
// Kernel 2: vectorized sampler (byte-identical hot loop to the 64us version).
// Block 0 additionally resets g_prep_done for the next replay (no readers of
// the flag exist after the previous kernel completed).
// ---------------------------------------------------------------------------
__global__ __launch_bounds__(256) void sample_kernel(
    const int*   __restrict__ mapping,
    float*       __restrict__ out)
{
    if (blockIdx.x == 0 && threadIdx.x == 0) g_prep_done = 0;

    const int lane = threadIdx.x & 31;
    const int wid  = (blockIdx.x << 3) + (threadIdx.x >> 5);
    const int s0   = wid << 5;                // 32 samples per warp
    const int k    = s0 >> 10;
    const int y    = (s0 >> 7) & 7;
    const int xs   = s0 & 127;                // 0,32,64,96

    const int box   = g_order[k];
    const int width = g_width[box];

    const int ch = (lane & 15) << 1;          // channel pair
    const int hp = (lane >> 4) << 4;          // 0 or 16
    float* const ob = out + (((size_t)(s0 + hp)) << 5) + ch;

    if (xs >= width) {
        const float2 z = make_float2(0.f, 0.f);
        #pragma unroll
        for (int it = 0; it < 16; it++)
            __stcs((float2*)(ob + ((size_t)it << 5)), z);
        return;
    }

    const int n = mapping[box];
    const __half* const fb = g_fmt + ((size_t)n * IMG_WORDS) + ch;

    // per-lane geometry for sample x = xs + lane
    const float fx = (float)(xs + lane);
    const float fy = (float)y;
    const float sx = g_p1x[box] + g_axx[box] * fx + g_ayx[box] * fy;
    const float sy = g_p1y[box] + g_axy[box] * fx + g_ayy[box] * fy;
    const float x0f = floorf(sx), y0f = floorf(sy);
    const float tx = sx - x0f, ty = sy - y0f;
    const int x0 = (int)x0f, y0 = (int)y0f;
    const bool act = (xs + lane) < width;
    const bool vx0 = ((unsigned)x0       < (unsigned)WF);
    const bool vx1 = ((unsigned)(x0 + 1) < (unsigned)WF);
    const bool vy0 = ((unsigned)y0       < (unsigned)HF);
    const bool vy1 = ((unsigned)(y0 + 1) < (unsigned)HF);
    float w00 = (1.f - tx) * (1.f - ty); if (!(vx0 & vy0 & act)) w00 = 0.f;
    float w01 = tx * (1.f - ty);         if (!(vx1 & vy0 & act)) w01 = 0.f;
    float w10 = (1.f - tx) * ty;         if (!(vx0 & vy1 & act)) w10 = 0.f;
    float w11 = tx * ty;                 if (!(vx1 & vy1 & act)) w11 = 0.f;
    const int xc0 = min(max(x0, 0), WF - 1);
    const int xc1 = min(max(x0 + 1, 0), WF - 1);
    const int yc0 = min(max(y0, 0), HF - 1);
    const int yc1 = min(max(y0 + 1, 0), HF - 1);
    // packed: o00 (32-aligned) | dx-bit | dy-bit<<1
    const int pk = ((yc0 << 13) + (xc0 << 5)) | (xc1 - xc0) | ((yc1 - yc0) << 1);

    const int sbase = lane & 16;              // shfl source offset
    #pragma unroll
    for (int it = 0; it < 16; it++) {
        const int src = it + sbase;
        const float W00 = __shfl_sync(0xffffffffu, w00, src);
        const float W01 = __shfl_sync(0xffffffffu, w01, src);
        const float W10 = __shfl_sync(0xffffffffu, w10, src);
        const float W11 = __shfl_sync(0xffffffffu, w11, src);
        const int   PK  = __shfl_sync(0xffffffffu, pk,  src);
        const int   O00 = PK & ~3;
        const int   DX  = (PK & 1) << 5;
        const int   DY  = (PK & 2) << 12;
        const __half* p = fb + O00;
        const float2 v00 = __half22float2(*(const __half2*)(p));
        const float2 v01 = __half22float2(*(const __half2*)(p + DX));
        const float2 v10 = __half22float2(*(const __half2*)(p + DY));
        const float2 v11 = __half22float2(*(const __half2*)(p + DX + DY));
        float2 r;
        r.x = W00 * v00.x + W01 * v01.x + W10 * v10.x + W11 * v11.x;
        r.y = W00 * v00.y + W01 * v01.y + W10 * v10.y + W11 * v11.y;
        __stcs((float2*)(ob + ((size_t)it << 5)), r);
    }
}

// ---------------------------------------------------------------------------
extern "C" void kernel_launch(void* const* d_in, const int* in_sizes, int n_in,
                              void* d_out, int out_size) {
    const float* fm      = (const float*)d_in[0];
    const float* boxes   = (const float*)d_in[1];
    const int*   mapping = (const int*)  d_in[2];
    float*       out     = (float*)d_out;

    const int M = in_sizes[1] / 8;  // 1024
    const size_t main_elems = (size_t)M * 8 * MAXW * CCH;
    const int write_tail = ((size_t)out_size >= main_elems + 2 * (size_t)M) ? 1 : 0;

    const int fm_elems  = in_sizes[0];                // N*C*H*W
    const int tr_blocks = fm_elems / (CCH * 64);      // 64 px per block

    fused_prep_transpose_rank_kernel<<<NB_PREP + NB_RANK + tr_blocks, 256>>>(
        fm, boxes, mapping, out + main_elems, M, write_tail);
    sample_kernel<<<M * 16 / 4, 256>>>(mapping, out);
}

// round 16
// speedup vs baseline: 1.2347x; 1.2347x over previous
#include <cuda_runtime.h>
#include <cuda_fp16.h>
#include <math.h>

#define CCH  32
#define HF   256
#define WF   256
#define MAXW 128
#define MBOX 1024
#define IMG_WORDS (32u * 65536u)           // elements per image (C*H*W)

// 67 MB transposed feature map scratch: layout (N, H, W, C), C contiguous, fp16.
// Fits in L2 (126 MB) -> sampler gathers are L2 hits if output writes stream.
__device__ __half g_fmt[16u * IMG_WORDS];

__device__ float g_p1x[MBOX], g_p1y[MBOX];
__device__ float g_axx[MBOX], g_axy[MBOX];
__device__ float g_ayx[MBOX], g_ayy[MBOX];
__device__ int   g_width[MBOX];
__device__ int   g_order[MBOX];
__device__ int4  g_bbox[MBOX];     // xmin, xmax, ymin, ymax (feature px, +margin)
__device__ int   g_map[MBOX];      // mapping (or -1 past M)

// ---------------------------------------------------------------------------
// Kernel 1: per-box width (bit-identical discrete math), geometry, bbox.
// ---------------------------------------------------------------------------
__global__ __launch_bounds__(256) void prep_kernel(
    const float* __restrict__ boxes, const int* __restrict__ mapping, int M)
{
    const int i = blockIdx.x * 256 + threadIdx.x;
    if (i >= MBOX) return;
    if (i >= M) {
        g_map[i]  = -1;
        g_bbox[i] = make_int4(1 << 30, -(1 << 30), 1 << 30, -(1 << 30));
        return;
    }
    const float* b = boxes + i * 8;
    float p1x = b[0]*0.25f, p1y = b[1]*0.25f;
    float p2x = b[2]*0.25f, p2y = b[3]*0.25f;
    float p4x = b[6]*0.25f, p4y = b[7]*0.25f;
    float dx2 = __fadd_rn(p2x,-p1x), dy2 = __fadd_rn(p2y,-p1y);
    float dx4 = __fadd_rn(p4x,-p1x), dy4 = __fadd_rn(p4y,-p1y);
    float bw = __fsqrt_rn(__fadd_rn(__fmul_rn(dx2,dx2), __fmul_rn(dy2,dy2)));
    float bh = __fsqrt_rn(__fadd_rn(__fmul_rn(dx4,dx4), __fmul_rn(dy4,dy4)));
    float bmaj = bw, bmin = bh;
    if (bw <= bh) { bmaj = bh; bmin = bw; }
    float ratio = __fdiv_rn(__fmul_rn(8.0f, bmaj), fmaxf(bmin, 1e-6f));
    int w = (int)fminf(fmaxf(ceilf(ratio), 1.0f), 128.0f);

    float wf = (float)w;
    g_width[i] = w;
    g_p1x[i] = p1x; g_p1y[i] = p1y;
    g_axx[i] = __fdiv_rn(dx2, wf);
    g_axy[i] = __fdiv_rn(dy2, wf);
    g_ayx[i] = dx4 * 0.125f;
    g_ayy[i] = dy4 * 0.125f;

    // bbox over the 4 corners (p3 = p2 + p4 - p1), margin 2 for bilinear taps
    float p3x = p2x + p4x - p1x, p3y = p2y + p4y - p1y;
    float xmn = fminf(fminf(p1x, p2x), fminf(p4x, p3x));
    float xmx = fmaxf(fmaxf(p1x, p2x), fmaxf(p4x, p3x));
    float ymn = fminf(fminf(p1y, p2y), fminf(p4y, p3y));
    float ymx = fmaxf(fmaxf(p1y, p2y), fmaxf(p4y, p3y));
    g_bbox[i] = make_int4((int)floorf(xmn) - 2, (int)ceilf(xmx) + 2,
                          (int)floorf(ymn) - 2, (int)ceilf(ymx) + 2);
    g_map[i] = mapping[i];
}

// ---------------------------------------------------------------------------
// Kernel 2: transpose with tile-skip + fused rank blocks.
// ---------------------------------------------------------------------------
__global__ __launch_bounds__(256) void transpose_rank_kernel(
    const float* __restrict__ fm, float* __restrict__ out_tail,
    int M, int write_tail, int tr_blocks)
{
    const int tid  = threadIdx.x;
    const int lane = tid & 31;
    const int wrp  = tid >> 5;

    if (blockIdx.x >= tr_blocks) {
        // ---------------- rank part ----------------
        __shared__ int sw[MBOX];
        for (int i = tid; i < MBOX; i += 256)
            sw[i] = (i < M) ? g_width[i] : -1;
        __syncthreads();
        const int i = (blockIdx.x - tr_blocks) * 8 + wrp;
        if (i < M) {
            const int w = sw[i];
            int rank = 0;
            #pragma unroll 4
            for (int t = 0; t < MBOX / 32; t++) {
                int j = t * 32 + lane;
                int wj = sw[j];
                rank += (wj > w) | ((wj == w) & (j < i));
            }
            #pragma unroll
            for (int o = 16; o; o >>= 1)
                rank += __shfl_xor_sync(0xffffffffu, rank, o);
            if (lane == 0) {
                g_order[rank] = i;
                if (write_tail) {
                    out_tail[rank]     = (float)w;
                    out_tail[M + rank] = (float)i;
                }
            }
        }
        return;
    }

    // ---------------- transpose part ----------------
    const int px0 = blockIdx.x << 6;          // 64 px per block
    const int n   = px0 >> 16;
    const int pxi = px0 & 65535;
    const int row = pxi >> 8;
    const int xq0 = pxi & 255;                // 0,64,128,192

    // skip test: does any box of image n touch this row-quarter?
    int pred = 0;
    #pragma unroll
    for (int t = 0; t < 4; t++) {
        const int bix = tid + (t << 8);
        const int4 bb = g_bbox[bix];
        const int  mp = g_map[bix];
        pred |= (mp == n) & (row >= bb.z) & (row <= bb.w)
                          & (xq0 <= bb.y) & (xq0 + 63 >= bb.x);
    }
    if (!__syncthreads_or(pred)) return;

    __shared__ float tile[32][65];
    const size_t ibase = (size_t)n * IMG_WORDS;

    // read: coalesced along W (read-once, evict-first)
    #pragma unroll
    for (int t = 0; t < 4; t++) {
        const int cc = wrp + t * 8;
        const float* src = fm + ibase + ((size_t)cc << 16) + pxi;
        tile[cc][lane]      = __ldcs(src + lane);
        tile[cc][lane + 32] = __ldcs(src + lane + 32);
    }
    __syncthreads();

    // write: coalesced along C, __half2 per lane (default policy: keep in L2)
    const int c0 = (lane & 15) << 1;
    const int pp = lane >> 4;
    __half* const dstb = g_fmt + ibase + ((size_t)pxi << 5) + c0;
    #pragma unroll
    for (int t = 0; t < 4; t++) {
        const int p0 = ((wrp + t * 8) << 1) + pp;     // 0..63
        __half2 v = __floats2half2_rn(tile[c0][p0], tile[c0 + 1][p0]);
        *(__half2*)(dstb + ((size_t)p0 << 5)) = v;
    }
}

// ---------------------------------------------------------------------------
// Kernel 3: 4-channel-vectorized sampler.  Warp = 32 consecutive x of one
// (slot, row); lane l computes geometry for sample x = xs + l.  Inner loop:
// iteration it covers samples it*4..it*4+3; lane = (sgrp, cq): sample
// subgroup (lane>>3) x channel-quad (lane&7).  Per tap: one 8B load (4 fp16
// channels); per sample: one float4 streaming store.  Packed offsets, one
// shfl for all three.
// ---------------------------------------------------------------------------
__global__ __launch_bounds__(256) void sample_kernel(
    const int*   __restrict__ mapping,
    float*       __restrict__ out)
{
    const int lane = threadIdx.x & 31;
    const int wid  = (blockIdx.x << 3) + (threadIdx.x >> 5);
    const int s0   = wid << 5;                // 32 samples per warp
    const int k    = s0 >> 10;
    const int y    = (s0 >> 7) & 7;
    const int xs   = s0 & 127;                // 0,32,64,96

    const int box   = g_order[k];
    const int width = g_width[box];

    const int sgrp = lane >> 3;               // sample subgroup 0..3
    const int cq   = lane & 7;                // channel quad 0..7
    float* const ob = out + ((size_t)s0 << 5) + (cq << 2);

    if (xs >= width) {
        const float4 z = make_float4(0.f, 0.f, 0.f, 0.f);
        #pragma unroll
        for (int it = 0; it < 8; it++) {
            const int s = (it << 2) + sgrp;
            __stcs((float4*)(ob + ((size_t)s << 5)), z);
        }
        return;
    }

    const int n = mapping[box];
    const __half* const fb = g_fmt + ((size_t)n * IMG_WORDS) + (cq << 2);

    // per-lane geometry for sample x = xs + lane
    const float fx = (float)(xs + lane);
    const float fy = (float)y;
    const float sx = g_p1x[box] + g_axx[box] * fx + g_ayx[box] * fy;
    const float sy = g_p1y[box] + g_axy[box] * fx + g_ayy[box] * fy;
    const float x0f = floorf(sx), y0f = floorf(sy);
    const float tx = sx - x0f, ty = sy - y0f;
    const int x0 = (int)x0f, y0 = (int)y0f;
    const bool act = (xs + lane) < width;
    const bool vx0 = ((unsigned)x0       < (unsigned)WF);
    const bool vx1 = ((unsigned)(x0 + 1) < (unsigned)WF);
    const bool vy0 = ((unsigned)y0       < (unsigned)HF);
    const bool vy1 = ((unsigned)(y0 + 1) < (unsigned)HF);
    float w00 = (1.f - tx) * (1.f - ty); if (!(vx0 & vy0 & act)) w00 = 0.f;
    float w01 = tx * (1.f - ty);         if (!(vx1 & vy0 & act)) w01 = 0.f;
    float w10 = (1.f - tx) * ty;         if (!(vx0 & vy1 & act)) w10 = 0.f;
    float w11 = tx * ty;                 if (!(vx1 & vy1 & act)) w11 = 0.f;
    const int xc0 = min(max(x0, 0), WF - 1);
    const int xc1 = min(max(x0 + 1, 0), WF - 1);
    const int yc0 = min(max(y0, 0), HF - 1);
    const int yc1 = min(max(y0 + 1, 0), HF - 1);
    // packed: o00 (32-aligned) | dx-bit | dy-bit<<1
    const int pk = ((yc0 << 13) + (xc0 << 5)) | (xc1 - xc0) | ((yc1 - yc0) << 1);

    #pragma unroll
    for (int it = 0; it < 8; it++) {
        const int src = (it << 2) + sgrp;     // this lane's sample for this iter
        const float W00 = __shfl_sync(0xffffffffu, w00, src);
        const float W01 = __shfl_sync(0xffffffffu, w01, src);
        const float W10 = __shfl_sync(0xffffffffu, w10, src);
        const float W11 = __shfl_sync(0xffffffffu, w11, src);
        const int   PK  = __shfl_sync(0xffffffffu, pk,  src);
        const int   O00 = PK & ~3;
        const int   DX  = (PK & 1) << 5;
        const int   DY  = (PK & 2) << 12;

        const uint2 a00 = *(const uint2*)(fb + O00);
        const uint2 a01 = *(const uint2*)(fb + O00 + DX);
        const uint2 a10 = *(const uint2*)(fb + O00 + DY);
        const uint2 a11 = *(const uint2*)(fb + O00 + DX + DY);

        const float2 l00 = __half22float2(*(const __half2*)&a00.x);
        const float2 h00 = __half22float2(*(const __half2*)&a00.y);
        const float2 l01 = __half22float2(*(const __half2*)&a01.x);
        const float2 h01 = __half22float2(*(const __half2*)&a01.y);
        const float2 l10 = __half22float2(*(const __half2*)&a10.x);
        const float2 h10 = __half22float2(*(const __half2*)&a10.y);
        const float2 l11 = __half22float2(*(const __half2*)&a11.x);
        const float2 h11 = __half22float2(*(const __half2*)&a11.y);

        float4 r;
        r.x = W00 * l00.x + W01 * l01.x + W10 * l10.x + W11 * l11.x;
        r.y = W00 * l00.y + W01 * l01.y + W10 * l10.y + W11 * l11.y;
        r.z = W00 * h00.x + W01 * h01.x + W10 * h10.x + W11 * h11.x;
        r.w = W00 * h00.y + W01 * h01.y + W10 * h10.y + W11 * h11.y;

        const int s = (it << 2) + sgrp;
        __stcs((float4*)(ob + ((size_t)s << 5)), r);
    }
}

// ---------------------------------------------------------------------------
extern "C" void kernel_launch(void* const* d_in, const int* in_sizes, int n_in,
                              void* d_out, int out_size) {
    const float* fm      = (const float*)d_in[0];
    const float* boxes   = (const float*)d_in[1];
    const int*   mapping = (const int*)  d_in[2];
    float*       out     = (float*)d_out;

    const int M = in_sizes[1] / 8;  // 1024
    const size_t main_elems = (size_t)M * 8 * MAXW * CCH;
    const int write_tail = ((size_t)out_size >= main_elems + 2 * (size_t)M) ? 1 : 0;

    const int fm_elems  = in_sizes[0];                // N*C*H*W
    const int tr_blocks = fm_elems / (CCH * 64);      // 64 px per block

    prep_kernel<<<4, 256>>>(boxes, mapping, M);
    transpose_rank_kernel<<<tr_blocks + 128, 256>>>(fm, out + main_elems, M, write_tail, tr_blocks);
    sample_kernel<<<M * 16 / 4, 256>>>(mapping, out);
}